// round 14
// baseline (speedup 1.0000x reference)
#include <cuda_runtime.h>
#include <cuda_bf16.h>
#include <math.h>
#include <stdint.h>

// Problem constants
#define BB   256
#define TT   1024
#define DD   256
#define UU   128
#define GG   384      // 3*U
#define MM   (BB*TT)  // 262144 rows

#define NBLK  148
#define NSCAN 32
#define NWORK (NBLK - NSCAN)   // 116
#define NJOB  8192             // 8 chunks x 256 batches x (3 gemm + 1 fgate)

// Scratch (device globals — no allocation allowed)
__device__ float g_xproj[(size_t)MM * GG];        // [B*T, 384]
__device__ float g_fg[(size_t)MM * UU];           // [B*T, 128]
__device__ __nv_bfloat16 g_bhi[(size_t)GG * DD];  // W^T hi: [384,256]
__device__ __nv_bfloat16 g_blo[(size_t)GG * DD];  // W^T lo
__device__ __nv_bfloat16 g_rk[(size_t)GG * UU];   // rk^T bf16 hi: [384,128]
__device__ int g_flags[8 * 256];                  // [chunk][batch] -> 4 = ready

// ---------------------------------------------------------------------------
__device__ __forceinline__ uint32_t s2u(const void* p) {
    uint32_t a;
    asm("{ .reg .u64 t; cvta.to.shared.u64 t, %1; cvt.u32.u64 %0, t; }"
        : "=r"(a) : "l"(p));
    return a;
}

#define SW128(o) ((o) ^ (((o) >> 3) & 0x70))

__device__ __forceinline__ void ldsm_x4(uint32_t* r, uint32_t addr) {
    asm volatile("ldmatrix.sync.aligned.m8n8.x4.shared.b16 {%0,%1,%2,%3}, [%4];"
                 : "=r"(r[0]), "=r"(r[1]), "=r"(r[2]), "=r"(r[3]) : "r"(addr));
}

__device__ __forceinline__ void mma_bf16(float* d, const uint32_t* a,
                                         const uint32_t* b) {
    asm volatile(
        "mma.sync.aligned.m16n8k16.row.col.f32.bf16.bf16.f32 "
        "{%0,%1,%2,%3}, {%4,%5,%6,%7}, {%8,%9}, {%0,%1,%2,%3};"
        : "+f"(d[0]), "+f"(d[1]), "+f"(d[2]), "+f"(d[3])
        : "r"(a[0]), "r"(a[1]), "r"(a[2]), "r"(a[3]), "r"(b[0]), "r"(b[1]));
}

__device__ __forceinline__ void cp16(uint32_t dst, const void* src) {
    asm volatile("cp.async.cg.shared.global [%0], [%1], 16;"
                 :: "r"(dst), "l"(src) : "memory");
}
__device__ __forceinline__ void cp_commit() {
    asm volatile("cp.async.commit_group;" ::: "memory");
}
template <int N>
__device__ __forceinline__ void cp_wait() {
    asm volatile("cp.async.wait_group %0;" :: "n"(N) : "memory");
}

__device__ __forceinline__ float tanh_apx(float x) {
    float y;
    asm("tanh.approx.f32 %0, %1;" : "=f"(y) : "f"(x));
    return y;
}
__device__ __forceinline__ float fsig(float x) {
    return __fdividef(1.0f, 1.0f + __expf(-x));
}

// one-instruction bf16x2 pack: result = {lo16 = bf16(a), hi16 = bf16(b)}
__device__ __forceinline__ uint32_t cvt2(float a, float b) {
    uint32_t r;
    asm("cvt.rn.bf16x2.f32 %0, %1, %2;" : "=r"(r) : "f"(b), "f"(a));
    return r;
}
// hi/lo split pair pack (identical rounding to __float2bfloat16 chain)
__device__ __forceinline__ void pack2(float a, float b, uint32_t& hi,
                                      uint32_t& lo) {
    hi = cvt2(a, b);
    const float fa = __uint_as_float(hi << 16);
    const float fb = __uint_as_float(hi & 0xFFFF0000u);
    lo = cvt2(a - fa, b - fb);
}

// ---------------------------------------------------------------------------
__global__ void zero_flags() {
    g_flags[blockIdx.x * 256 + threadIdx.x] = 0;
}

// transpose + split input_kernel W[256,384] -> [384,256]
__global__ __launch_bounds__(256) void convert_b(const float* __restrict__ W) {
    int n = blockIdx.x;
    int k = threadIdx.x;
    float v = W[(size_t)k * GG + n];
    __nv_bfloat16 h = __float2bfloat16(v);
    __nv_bfloat16 l = __float2bfloat16(v - __bfloat162float(h));
    g_bhi[(size_t)n * DD + k] = h;
    g_blo[(size_t)n * DD + k] = l;
}

// transpose recurrent_kernel rk[128,384] -> bf16 [384,128]
__global__ __launch_bounds__(128) void convert_rk(const float* __restrict__ rk) {
    int n = blockIdx.x;
    int k = threadIdx.x;
    g_rk[(size_t)n * UU + k] = __float2bfloat16(rk[(size_t)k * GG + n]);
}

// ---------------------------------------------------------------------------
// GEMM worker tile (512 threads, 16 warps x 32x32 warp tiles).
// smem: 2 buffers x (Ahi|Alo|Bhi|Blo, 16KB each) = 128KB; sig region at 128KB.
// ---------------------------------------------------------------------------
#define FK_OFF 131072
#define MEGA_SMEM (FK_OFF + 128 * 20 * 4)

__device__ __forceinline__ void ldA(const float* __restrict__ inputs, int row0,
                                    int k0, int tid, float4* fa) {
#pragma unroll
    for (int i = 0; i < 2; ++i) {
        const int u = tid + i * 512;
        const int row = u >> 3, c16 = u & 7;
        const float4* src =
            (const float4*)&inputs[(size_t)(row0 + row) * DD + k0 + c16 * 8];
        fa[2 * i]     = src[0];
        fa[2 * i + 1] = src[1];
    }
}

__device__ __forceinline__ void stA(char* dsm, uint32_t base, int tid,
                                    const float4* fa) {
#pragma unroll
    for (int i = 0; i < 2; ++i) {
        const int u = tid + i * 512;
        const int row = u >> 3, c16 = u & 7;
        const float4 a = fa[2 * i], b = fa[2 * i + 1];
        uint4 hi, lo;
        pack2(a.x, a.y, hi.x, lo.x);
        pack2(a.z, a.w, hi.y, lo.y);
        pack2(b.x, b.y, hi.z, lo.z);
        pack2(b.z, b.w, hi.w, lo.w);
        const uint32_t so = SW128((uint32_t)(row * 128 + c16 * 16));
        *(uint4*)(dsm + base + so)         = hi;
        *(uint4*)(dsm + base + 16384 + so) = lo;
    }
}

__device__ __forceinline__ void ldB(uint32_t sb, int buf, int k0, int n0g,
                                    int tid) {
    const uint32_t base = sb + buf * 65536;
#pragma unroll
    for (int i = 0; i < 2; ++i) {
        const int id  = tid + i * 512;
        const int row = id >> 3;
        const int c16 = id & 7;
        const uint32_t so = SW128((uint32_t)(row * 128 + c16 * 16));
        const size_t boff = (size_t)(n0g + row) * DD + k0 + c16 * 8;
        cp16(base + 32768 + so, g_bhi + boff);
        cp16(base + 49152 + so, g_blo + boff);
    }
}

__device__ void gemm_tile(char* dsm, const float* __restrict__ inputs,
                          int n0g, int row0, int tid) {
    const uint32_t sb = s2u(dsm);
    const int wid  = tid >> 5;
    const int lane = tid & 31;

    const int m0w = (wid >> 2) * 32;   // 0,32,64,96
    const int n0w = (wid & 3) * 32;

    float acc[2][4][4];
#pragma unroll
    for (int i = 0; i < 2; ++i)
#pragma unroll
        for (int j = 0; j < 4; ++j)
#pragma unroll
            for (int k = 0; k < 4; ++k) acc[i][j][k] = 0.f;

    const int a_lr = lane & 15;
    const int a_lc = (lane >> 4) * 16;
    const int b_lr = ((lane >> 4) << 3) + (lane & 7);
    const int b_lc = ((lane >> 3) & 1) * 16;

    {
        float4 fa[4];
        ldA(inputs, row0, 0, tid, fa);
        ldB(sb, 0, 0, n0g, tid);
        cp_commit();
        stA(dsm, 0, tid, fa);
        cp_wait<0>();
        __syncthreads();
    }

#pragma unroll
    for (int c = 0; c < 4; ++c) {
        float4 fa[4];
        if (c < 3) {
            ldA(inputs, row0, (c + 1) * 64, tid, fa);
            ldB(sb, (c + 1) & 1, (c + 1) * 64, n0g, tid);
            cp_commit();
        }

        const uint32_t ab  = sb + (c & 1) * 65536;
        const uint32_t alb = ab + 16384;
        const uint32_t bhb = ab + 32768;
        const uint32_t blb = ab + 49152;

#pragma unroll
        for (int kf = 0; kf < 4; ++kf) {
            uint32_t ah[2][4], al[2][4], bh[2][4], bl[2][4];
#pragma unroll
            for (int mf = 0; mf < 2; ++mf) {
                const uint32_t off =
                    SW128((uint32_t)((m0w + mf * 16 + a_lr) * 128 + kf * 32 + a_lc));
                ldsm_x4(ah[mf], ab + off);
                ldsm_x4(al[mf], alb + off);
            }
#pragma unroll
            for (int nf2 = 0; nf2 < 2; ++nf2) {
                const uint32_t off =
                    SW128((uint32_t)((n0w + nf2 * 16 + b_lr) * 128 + kf * 32 + b_lc));
                ldsm_x4(bh[nf2], bhb + off);
                ldsm_x4(bl[nf2], blb + off);
            }
#pragma unroll
            for (int mf = 0; mf < 2; ++mf)
#pragma unroll
                for (int nf = 0; nf < 4; ++nf) {
                    const uint32_t* bhp = &bh[nf >> 1][(nf & 1) * 2];
                    const uint32_t* blp = &bl[nf >> 1][(nf & 1) * 2];
                    mma_bf16(acc[mf][nf], ah[mf], bhp);
                    mma_bf16(acc[mf][nf], ah[mf], blp);
                    mma_bf16(acc[mf][nf], al[mf], bhp);
                }
        }

        if (c < 3) {
            __syncthreads();
            stA(dsm, ((c + 1) & 1) * 65536, tid, fa);
            cp_wait<0>();
        }
        __syncthreads();
    }

#pragma unroll
    for (int mf = 0; mf < 2; ++mf) {
        const int rg = row0 + m0w + mf * 16 + (lane >> 2);
#pragma unroll
        for (int nf = 0; nf < 4; ++nf) {
            const int cg = n0g + n0w + nf * 8 + ((lane & 3) << 1);
            *(float2*)&g_xproj[(size_t)rg * GG + cg] =
                make_float2(acc[mf][nf][0], acc[mf][nf][1]);
            *(float2*)&g_xproj[(size_t)(rg + 8) * GG + cg] =
                make_float2(acc[mf][nf][2], acc[mf][nf][3]);
        }
    }
}

// f-tile: fg for (batch b, t in [chunk*128, +128)).
__device__ void f_tile(char* dsm, const float* __restrict__ sig,
                       const float* wk, float bf, int b, int chunk, int tid) {
    float* ss = (float*)(dsm + FK_OFF);
    const size_t bt0 = (size_t)b * TT + chunk * 128;
    for (int i = tid; i < 128 * 20; i += 512)
        ss[i] = sig[bt0 * 20 + i];
    __syncthreads();
    const int u  = tid & 127;
    const int th = tid >> 7;
#pragma unroll 4
    for (int i = 0; i < 32; ++i) {
        const int t = th * 32 + i;
        float s = bf;
        const float* sr = ss + t * 20;
#pragma unroll
        for (int k = 0; k < 20; ++k) s = fmaf(sr[k], wk[k], s);
        g_fg[(bt0 + t) * UU + u] = fsig(s);
    }
}

// ---------------------------------------------------------------------------
// Scan body: 512 threads (16 warps), split accumulators (RAW chain 8->4),
// cvt.rn.bf16x2 packing, STS-before-STG tail.
// ---------------------------------------------------------------------------
#define XS_ROW 388
#define XS_F   (8 * XS_ROW)  // 3104
#define FS_ROW 132
#define FS_F   (8 * FS_ROW)  // 1056
#define AS_ROW 144
#define AS_W   (8 * AS_ROW)  // 1152 u32 per buffer
#define XS_OFF 0
#define FS_OFF (2 * XS_F)
#define AS_OFF (2 * XS_F + 2 * FS_F)

__device__ __forceinline__ void wait_chunk(int c, int b0g, int tid) {
    if (tid < 8) {
        volatile int* f = (volatile int*)&g_flags[c * 256 + b0g + tid];
        while (*f < 4) {}
        __threadfence();
    }
}

__device__ void scan_body(char* dsm, const float* __restrict__ bias,
                          float* __restrict__ out, int bid, int tid) {
    float* sm = (float*)dsm;
    float* xs = sm + XS_OFF;
    float* fs = sm + FS_OFF;
    uint32_t* As = (uint32_t*)(sm + AS_OFF);
    const uint32_t smu = s2u(sm);

    const int wid  = tid >> 5;
    const int lane = tid & 31;
    const int b0g  = bid * 8;

    for (int i = tid; i < 2 * AS_W; i += 512) As[i] = 0;

    // rk B-fragments: col n = nc*128 + 8*wid + (lane>>2)
    uint32_t wfr[8][3][2];
#pragma unroll
    for (int kc = 0; kc < 8; ++kc)
#pragma unroll
        for (int nc = 0; nc < 3; ++nc) {
            const int n = nc * 128 + 8 * wid + (lane >> 2);
            const int k = kc * 16 + (lane & 3) * 2;
            wfr[kc][nc][0] = *(const uint32_t*)&g_rk[(size_t)n * UU + k];
            wfr[kc][nc][1] = *(const uint32_t*)&g_rk[(size_t)n * UU + k + 8];
        }

    float bb0[3], bb1[3], pp[3];
#pragma unroll
    for (int nc = 0; nc < 3; ++nc) {
        const int c = nc * 128 + 8 * wid + (lane & 3) * 2;
        bb0[nc] = (c < UU) ? bias[c] : bias[c + UU];
        bb1[nc] = (c + 1 < UU) ? bias[c + 1] : bias[c + 1 + UU];
        pp[nc]  = (nc == 1) ? 1.0f : 0.5f;
    }

    float cst[2] = {0.f, 0.f};

#define PREFETCH(t)                                                            \
    {                                                                          \
        const int _buf = (t) & 1;                                              \
        {                                                                      \
            const int r = tid / 96, o = tid % 96;                              \
            cp16(smu + (XS_OFF + _buf * XS_F + r * XS_ROW + o * 4) * 4,        \
                 &g_xproj[((size_t)(b0g + r) * TT + (t)) * GG + o * 4]);       \
        }                                                                      \
        {                                                                      \
            const int id = tid + 512;                                          \
            if (id < 768) {                                                    \
                const int r = id / 96, o = id % 96;                            \
                cp16(smu + (XS_OFF + _buf * XS_F + r * XS_ROW + o * 4) * 4,    \
                     &g_xproj[((size_t)(b0g + r) * TT + (t)) * GG + o * 4]);   \
            }                                                                  \
        }                                                                      \
        if (tid < 256) {                                                       \
            cp16(smu + (FS_OFF + _buf * FS_F + (tid >> 5) * FS_ROW +           \
                        (tid & 31) * 4) * 4,                                   \
                 &g_fg[((size_t)(b0g + (tid >> 5)) * TT + (t)) * UU +          \
                       (tid & 31) * 4]);                                       \
        }                                                                      \
        cp_commit();                                                           \
    }

    wait_chunk(0, b0g, tid);
    __syncthreads();
    PREFETCH(0);

    const int brow = lane >> 2;
    const int q4   = (lane & 3) * 4;
    const int ucol = 8 * wid + (lane & 3) * 2;
    const int wsl  = (wid >> 1) * 16 + q4 + (wid & 1) * 2;   // STS.64 slot

    for (int t = 0; t < TT; ++t) {
        cp_wait<0>();
        __syncthreads();

        const uint32_t* Ar = As + (t & 1) * AS_W;
        uint32_t* Aw = As + ((t + 1) & 1) * AS_W;

        const float* xb = xs + (t & 1) * XS_F + brow * XS_ROW;
        float accA[3][4], accB[3][4];
#pragma unroll
        for (int nc = 0; nc < 3; ++nc) {
            const float2 xv = *(const float2*)&xb[nc * 128 + ucol];
            accA[nc][0] = xv.x; accA[nc][1] = xv.y;
            accA[nc][2] = 0.f;  accA[nc][3] = 0.f;
            accB[nc][0] = 0.f;  accB[nc][1] = 0.f;
            accB[nc][2] = 0.f;  accB[nc][3] = 0.f;
        }

        if (t + 1 < TT) {
            if (((t + 1) & 127) == 0) {
                wait_chunk((t + 1) >> 7, b0g, tid);
                __syncthreads();
            }
            PREFETCH(t + 1);
        }

        // gates: two interleaved half-depth chains (kc and kc+4)
#pragma unroll
        for (int kc = 0; kc < 4; ++kc) {
            const uint4 avA = *(const uint4*)&Ar[brow * AS_ROW + kc * 16 + q4];
            const uint4 avB =
                *(const uint4*)&Ar[brow * AS_ROW + (kc + 4) * 16 + q4];
            uint32_t afA[4] = {avA.x, avA.y, avA.z, avA.w};
            uint32_t afB[4] = {avB.x, avB.y, avB.z, avB.w};
#pragma unroll
            for (int nc = 0; nc < 3; ++nc) {
                mma_bf16(accA[nc], afA, wfr[kc][nc]);
                mma_bf16(accB[nc], afB, wfr[kc + 4][nc]);
            }
        }

        float gv[3][2];
#pragma unroll
        for (int nc = 0; nc < 3; ++nc) {
            const float p = pp[nc], q = 1.0f - p;
            const float g0 =
                (accA[nc][0] + accA[nc][2]) + (accB[nc][0] + accB[nc][2]) + bb0[nc];
            const float g1 =
                (accA[nc][1] + accA[nc][3]) + (accB[nc][1] + accB[nc][3]) + bb1[nc];
            gv[nc][0] = fmaf(tanh_apx(g0 * p), p, q);
            gv[nc][1] = fmaf(tanh_apx(g1 * p), p, q);
        }

        const float2 fv =
            *(const float2*)&fs[(t & 1) * FS_F + brow * FS_ROW + ucol];
        cst[0] = fmaf(fv.x, cst[0], gv[0][0] * gv[1][0]);
        cst[1] = fmaf(fv.y, cst[1], gv[0][1] * gv[1][1]);
        const float h0 = gv[2][0] * tanh_apx(cst[0]);
        const float h1 = gv[2][1] * tanh_apx(cst[1]);

        // critical path first: pack + STS to As
        uint2 hv;
        pack2(h0, h1, hv.x, hv.y);
        *(uint2*)&Aw[brow * AS_ROW + wsl] = hv;

        // off-path: output store
        *(float2*)&out[((size_t)(b0g + brow) * TT + t) * UU + ucol] =
            make_float2(h0, h1);
    }
}

// ---------------------------------------------------------------------------
// Megakernel: one wave of 148 CTAs (141KB smem => 1 CTA/SM).
// bids [0,32): scan. bids [32,148): workers over 8192 jobs, chunk-major:
// job = (chunk, batch, kind); kind 0..2 = gemm N-tiles, kind 3 = fgate tile.
// ---------------------------------------------------------------------------
__global__ __launch_bounds__(512, 1)
void mega_kernel(const float* __restrict__ inputs,
                 const float* __restrict__ signatures,
                 const float* __restrict__ fkern,
                 const float* __restrict__ bias,
                 float* __restrict__ out) {
    extern __shared__ __align__(16) char dsm[];
    const int bid = blockIdx.x;
    const int tid = threadIdx.x;

    if (bid < NSCAN) {
        scan_body(dsm, bias, out, bid, tid);
    } else {
        float wk[20];
        const int uf = tid & 127;
#pragma unroll
        for (int k = 0; k < 20; ++k) wk[k] = __ldg(&fkern[k * UU + uf]);
        const float bf = __ldg(&bias[UU + uf]);

        for (int tau = bid - NSCAN; tau < NJOB; tau += NWORK) {
            const int chunk = tau >> 10;
            const int j     = tau & 1023;
            const int b     = j >> 2;
            const int kind  = j & 3;
            if (kind < 3) {
                gemm_tile(dsm, inputs, kind * 128, b * 1024 + chunk * 128, tid);
            } else {
                f_tile(dsm, signatures, wk, bf, b, chunk, tid);
            }
            __syncthreads();
            if (tid == 0) {
                __threadfence();
                atomicAdd(&g_flags[chunk * 256 + b], 1);
            }
        }
    }
}

// ---------------------------------------------------------------------------
extern "C" void kernel_launch(void* const* d_in, const int* in_sizes, int n_in,
                              void* d_out, int out_size) {
    const float* inputs     = (const float*)d_in[0];
    const float* signatures = (const float*)d_in[1];
    const float* ikern      = (const float*)d_in[2];
    const float* rkern      = (const float*)d_in[3];
    const float* fkern      = (const float*)d_in[4];
    const float* bias       = (const float*)d_in[5];
    float* out = (float*)d_out;

    (void)in_sizes; (void)n_in; (void)out_size;

    static bool init = false;
    if (!init) {
        cudaFuncSetAttribute(mega_kernel,
                             cudaFuncAttributeMaxDynamicSharedMemorySize,
                             MEGA_SMEM);
        init = true;
    }

    zero_flags<<<8, 256>>>();
    convert_b<<<GG, DD>>>(ikern);
    convert_rk<<<GG, UU>>>(rkern);
    mega_kernel<<<NBLK, 512, MEGA_SMEM>>>(inputs, signatures, fkern, bias, out);
}

// round 16
// speedup vs baseline: 1.0222x; 1.0222x over previous
#include <cuda_runtime.h>
#include <cuda_bf16.h>
#include <math.h>
#include <stdint.h>

// Problem constants
#define BB   256
#define TT   1024
#define DD   256
#define UU   128
#define GG   384      // 3*U
#define MM   (BB*TT)  // 262144 rows

#define NBLK  148
#define NSCAN 32
#define NWORK (NBLK - NSCAN)   // 116
#define NJOB  8192             // 8 chunks x 256 batches x (3 gemm + 1 fgate)

// Scratch (device globals — no allocation allowed)
__device__ float g_xproj[(size_t)MM * GG];        // [B*T, 384] (bias folded in)
__device__ float g_fg[(size_t)MM * UU];           // [B*T, 128]
__device__ __nv_bfloat16 g_bhi[(size_t)GG * DD];  // W^T hi: [384,256]
__device__ __nv_bfloat16 g_blo[(size_t)GG * DD];  // W^T lo
__device__ int g_flags[8 * 256];                  // [chunk][batch] -> 4 = ready
                                                  // zero at load; scan re-zeroes

// ---------------------------------------------------------------------------
__device__ __forceinline__ uint32_t s2u(const void* p) {
    uint32_t a;
    asm("{ .reg .u64 t; cvta.to.shared.u64 t, %1; cvt.u32.u64 %0, t; }"
        : "=r"(a) : "l"(p));
    return a;
}

#define SW128(o) ((o) ^ (((o) >> 3) & 0x70))

__device__ __forceinline__ void ldsm_x4(uint32_t* r, uint32_t addr) {
    asm volatile("ldmatrix.sync.aligned.m8n8.x4.shared.b16 {%0,%1,%2,%3}, [%4];"
                 : "=r"(r[0]), "=r"(r[1]), "=r"(r[2]), "=r"(r[3]) : "r"(addr));
}

__device__ __forceinline__ void mma_bf16(float* d, const uint32_t* a,
                                         const uint32_t* b) {
    asm volatile(
        "mma.sync.aligned.m16n8k16.row.col.f32.bf16.bf16.f32 "
        "{%0,%1,%2,%3}, {%4,%5,%6,%7}, {%8,%9}, {%0,%1,%2,%3};"
        : "+f"(d[0]), "+f"(d[1]), "+f"(d[2]), "+f"(d[3])
        : "r"(a[0]), "r"(a[1]), "r"(a[2]), "r"(a[3]), "r"(b[0]), "r"(b[1]));
}

__device__ __forceinline__ void cp16(uint32_t dst, const void* src) {
    asm volatile("cp.async.cg.shared.global [%0], [%1], 16;"
                 :: "r"(dst), "l"(src) : "memory");
}
__device__ __forceinline__ void cp_commit() {
    asm volatile("cp.async.commit_group;" ::: "memory");
}
template <int N>
__device__ __forceinline__ void cp_wait() {
    asm volatile("cp.async.wait_group %0;" :: "n"(N) : "memory");
}

__device__ __forceinline__ float tanh_apx(float x) {
    float y;
    asm("tanh.approx.f32 %0, %1;" : "=f"(y) : "f"(x));
    return y;
}
__device__ __forceinline__ float fsig(float x) {
    return __fdividef(1.0f, 1.0f + __expf(-x));
}

// one-instruction bf16x2 pack: result = {lo16 = bf16(a), hi16 = bf16(b)}
__device__ __forceinline__ uint32_t cvt2(float a, float b) {
    uint32_t r;
    asm("cvt.rn.bf16x2.f32 %0, %1, %2;" : "=r"(r) : "f"(b), "f"(a));
    return r;
}
// hi/lo split pair pack (identical rounding to __float2bfloat16 chain)
__device__ __forceinline__ void pack2(float a, float b, uint32_t& hi,
                                      uint32_t& lo) {
    hi = cvt2(a, b);
    const float fa = __uint_as_float(hi << 16);
    const float fb = __uint_as_float(hi & 0xFFFF0000u);
    lo = cvt2(a - fa, b - fb);
}

// ---------------------------------------------------------------------------
// transpose + split input_kernel W[256,384] -> [384,256]  (only pre-kernel)
// ---------------------------------------------------------------------------
__global__ __launch_bounds__(256) void convert_b(const float* __restrict__ W) {
    int n = blockIdx.x;
    int k = threadIdx.x;
    float v = W[(size_t)k * GG + n];
    __nv_bfloat16 h = __float2bfloat16(v);
    __nv_bfloat16 l = __float2bfloat16(v - __bfloat162float(h));
    g_bhi[(size_t)n * DD + k] = h;
    g_blo[(size_t)n * DD + k] = l;
}

// ---------------------------------------------------------------------------
// GEMM worker tile (512 threads, 16 warps x 32x32 warp tiles).
// smem: 2 buffers x (Ahi|Alo|Bhi|Blo, 16KB each) = 128KB; sig region at 128KB.
// Epilogue adds bias (i/c/o regions) so the scan doesn't have to.
// ---------------------------------------------------------------------------
#define FK_OFF 131072
#define MEGA_SMEM (FK_OFF + 128 * 20 * 4)

__device__ __forceinline__ void ldA(const float* __restrict__ inputs, int row0,
                                    int k0, int tid, float4* fa) {
#pragma unroll
    for (int i = 0; i < 2; ++i) {
        const int u = tid + i * 512;
        const int row = u >> 3, c16 = u & 7;
        const float4* src =
            (const float4*)&inputs[(size_t)(row0 + row) * DD + k0 + c16 * 8];
        fa[2 * i]     = src[0];
        fa[2 * i + 1] = src[1];
    }
}

__device__ __forceinline__ void stA(char* dsm, uint32_t base, int tid,
                                    const float4* fa) {
#pragma unroll
    for (int i = 0; i < 2; ++i) {
        const int u = tid + i * 512;
        const int row = u >> 3, c16 = u & 7;
        const float4 a = fa[2 * i], b = fa[2 * i + 1];
        uint4 hi, lo;
        pack2(a.x, a.y, hi.x, lo.x);
        pack2(a.z, a.w, hi.y, lo.y);
        pack2(b.x, b.y, hi.z, lo.z);
        pack2(b.z, b.w, hi.w, lo.w);
        const uint32_t so = SW128((uint32_t)(row * 128 + c16 * 16));
        *(uint4*)(dsm + base + so)         = hi;
        *(uint4*)(dsm + base + 16384 + so) = lo;
    }
}

__device__ __forceinline__ void ldB(uint32_t sb, int buf, int k0, int n0g,
                                    int tid) {
    const uint32_t base = sb + buf * 65536;
#pragma unroll
    for (int i = 0; i < 2; ++i) {
        const int id  = tid + i * 512;
        const int row = id >> 3;
        const int c16 = id & 7;
        const uint32_t so = SW128((uint32_t)(row * 128 + c16 * 16));
        const size_t boff = (size_t)(n0g + row) * DD + k0 + c16 * 8;
        cp16(base + 32768 + so, g_bhi + boff);
        cp16(base + 49152 + so, g_blo + boff);
    }
}

__device__ void gemm_tile(char* dsm, const float* __restrict__ inputs,
                          const float* __restrict__ bias,
                          int n0g, int row0, int tid) {
    const uint32_t sb = s2u(dsm);
    const int wid  = tid >> 5;
    const int lane = tid & 31;

    const int m0w = (wid >> 2) * 32;   // 0,32,64,96
    const int n0w = (wid & 3) * 32;

    float acc[2][4][4];
#pragma unroll
    for (int i = 0; i < 2; ++i)
#pragma unroll
        for (int j = 0; j < 4; ++j)
#pragma unroll
            for (int k = 0; k < 4; ++k) acc[i][j][k] = 0.f;

    const int a_lr = lane & 15;
    const int a_lc = (lane >> 4) * 16;
    const int b_lr = ((lane >> 4) << 3) + (lane & 7);
    const int b_lc = ((lane >> 3) & 1) * 16;

    {
        float4 fa[4];
        ldA(inputs, row0, 0, tid, fa);
        ldB(sb, 0, 0, n0g, tid);
        cp_commit();
        stA(dsm, 0, tid, fa);
        cp_wait<0>();
        __syncthreads();
    }

#pragma unroll
    for (int c = 0; c < 4; ++c) {
        float4 fa[4];
        if (c < 3) {
            ldA(inputs, row0, (c + 1) * 64, tid, fa);
            ldB(sb, (c + 1) & 1, (c + 1) * 64, n0g, tid);
            cp_commit();
        }

        const uint32_t ab  = sb + (c & 1) * 65536;
        const uint32_t alb = ab + 16384;
        const uint32_t bhb = ab + 32768;
        const uint32_t blb = ab + 49152;

#pragma unroll
        for (int kf = 0; kf < 4; ++kf) {
            uint32_t ah[2][4], al[2][4], bh[2][4], bl[2][4];
#pragma unroll
            for (int mf = 0; mf < 2; ++mf) {
                const uint32_t off =
                    SW128((uint32_t)((m0w + mf * 16 + a_lr) * 128 + kf * 32 + a_lc));
                ldsm_x4(ah[mf], ab + off);
                ldsm_x4(al[mf], alb + off);
            }
#pragma unroll
            for (int nf2 = 0; nf2 < 2; ++nf2) {
                const uint32_t off =
                    SW128((uint32_t)((n0w + nf2 * 16 + b_lr) * 128 + kf * 32 + b_lc));
                ldsm_x4(bh[nf2], bhb + off);
                ldsm_x4(bl[nf2], blb + off);
            }
#pragma unroll
            for (int mf = 0; mf < 2; ++mf)
#pragma unroll
                for (int nf = 0; nf < 4; ++nf) {
                    const uint32_t* bhp = &bh[nf >> 1][(nf & 1) * 2];
                    const uint32_t* blp = &bl[nf >> 1][(nf & 1) * 2];
                    mma_bf16(acc[mf][nf], ah[mf], bhp);
                    mma_bf16(acc[mf][nf], ah[mf], blp);
                    mma_bf16(acc[mf][nf], al[mf], bhp);
                }
        }

        if (c < 3) {
            __syncthreads();
            stA(dsm, ((c + 1) & 1) * 65536, tid, fa);
            cp_wait<0>();
        }
        __syncthreads();
    }

#pragma unroll
    for (int mf = 0; mf < 2; ++mf) {
        const int rg = row0 + m0w + mf * 16 + (lane >> 2);
#pragma unroll
        for (int nf = 0; nf < 4; ++nf) {
            const int cg = n0g + n0w + nf * 8 + ((lane & 3) << 1);
            // fold bias (i:0-127 -> bias[cg]; c,o -> bias[cg+128])
            const int bix = cg + ((cg >= UU) ? UU : 0);
            const float b0 = __ldg(&bias[bix]);
            const float b1 = __ldg(&bias[bix + 1]);
            *(float2*)&g_xproj[(size_t)rg * GG + cg] =
                make_float2(acc[mf][nf][0] + b0, acc[mf][nf][1] + b1);
            *(float2*)&g_xproj[(size_t)(rg + 8) * GG + cg] =
                make_float2(acc[mf][nf][2] + b0, acc[mf][nf][3] + b1);
        }
    }
}

// f-tile: fg for (batch b, t in [chunk*128, +128)).
__device__ void f_tile(char* dsm, const float* __restrict__ sig,
                       const float* wk, float bf, int b, int chunk, int tid) {
    float* ss = (float*)(dsm + FK_OFF);
    const size_t bt0 = (size_t)b * TT + chunk * 128;
    for (int i = tid; i < 128 * 20; i += 512)
        ss[i] = sig[bt0 * 20 + i];
    __syncthreads();
    const int u  = tid & 127;
    const int th = tid >> 7;
#pragma unroll 4
    for (int i = 0; i < 32; ++i) {
        const int t = th * 32 + i;
        float s = bf;
        const float* sr = ss + t * 20;
#pragma unroll
        for (int k = 0; k < 20; ++k) s = fmaf(sr[k], wk[k], s);
        g_fg[(bt0 + t) * UU + u] = fsig(s);
    }
}

// ---------------------------------------------------------------------------
// Scan body: 512 threads (16 warps), round-13 structure; bias pre-folded into
// x_proj; cvt2 fast pack; STS-before-STG; rk fragments built from fp32 rkern;
// zeroes its own flags at end (keeps g_flags==0 invariant across replays).
// ---------------------------------------------------------------------------
#define XS_ROW 388
#define XS_F   (8 * XS_ROW)  // 3104
#define FS_ROW 132
#define FS_F   (8 * FS_ROW)  // 1056
#define AS_ROW 144
#define AS_W   (8 * AS_ROW)  // 1152 u32 per buffer
#define XS_OFF 0
#define FS_OFF (2 * XS_F)
#define AS_OFF (2 * XS_F + 2 * FS_F)

__device__ __forceinline__ void wait_chunk(int c, int b0g, int tid) {
    if (tid < 8) {
        volatile int* f = (volatile int*)&g_flags[c * 256 + b0g + tid];
        while (*f < 4) {}
        __threadfence();
    }
}

__device__ void scan_body(char* dsm, const float* __restrict__ rkern,
                          float* __restrict__ out, int bid, int tid) {
    float* sm = (float*)dsm;
    float* xs = sm + XS_OFF;
    float* fs = sm + FS_OFF;
    uint32_t* As = (uint32_t*)(sm + AS_OFF);
    const uint32_t smu = s2u(sm);

    const int wid  = tid >> 5;
    const int lane = tid & 31;
    const int b0g  = bid * 8;

    for (int i = tid; i < 2 * AS_W; i += 512) As[i] = 0;

    // rk B-fragments from fp32: col n = nc*128 + 8*wid + (lane>>2)
    uint32_t wfr[8][3][2];
#pragma unroll
    for (int kc = 0; kc < 8; ++kc)
#pragma unroll
        for (int nc = 0; nc < 3; ++nc) {
            const int n = nc * 128 + 8 * wid + (lane >> 2);
            const int k = kc * 16 + (lane & 3) * 2;
            wfr[kc][nc][0] = cvt2(__ldg(&rkern[(size_t)k * GG + n]),
                                  __ldg(&rkern[(size_t)(k + 1) * GG + n]));
            wfr[kc][nc][1] = cvt2(__ldg(&rkern[(size_t)(k + 8) * GG + n]),
                                  __ldg(&rkern[(size_t)(k + 9) * GG + n]));
        }

    float pp[3], qq[3];
#pragma unroll
    for (int nc = 0; nc < 3; ++nc) {
        pp[nc] = (nc == 1) ? 1.0f : 0.5f;
        qq[nc] = 1.0f - pp[nc];
    }

    float cst[2] = {0.f, 0.f};

#define PREFETCH(t)                                                            \
    {                                                                          \
        const int _buf = (t) & 1;                                              \
        {                                                                      \
            const int r = tid / 96, o = tid % 96;                              \
            cp16(smu + (XS_OFF + _buf * XS_F + r * XS_ROW + o * 4) * 4,        \
                 &g_xproj[((size_t)(b0g + r) * TT + (t)) * GG + o * 4]);       \
        }                                                                      \
        {                                                                      \
            const int id = tid + 512;                                          \
            if (id < 768) {                                                    \
                const int r = id / 96, o = id % 96;                            \
                cp16(smu + (XS_OFF + _buf * XS_F + r * XS_ROW + o * 4) * 4,    \
                     &g_xproj[((size_t)(b0g + r) * TT + (t)) * GG + o * 4]);   \
            }                                                                  \
        }                                                                      \
        if (tid < 256) {                                                       \
            cp16(smu + (FS_OFF + _buf * FS_F + (tid >> 5) * FS_ROW +           \
                        (tid & 31) * 4) * 4,                                   \
                 &g_fg[((size_t)(b0g + (tid >> 5)) * TT + (t)) * UU +          \
                       (tid & 31) * 4]);                                       \
        }                                                                      \
        cp_commit();                                                           \
    }

    wait_chunk(0, b0g, tid);
    __syncthreads();
    PREFETCH(0);

    const int brow = lane >> 2;
    const int q4   = (lane & 3) * 4;
    const int ucol = 8 * wid + (lane & 3) * 2;
    const int wsl  = (wid >> 1) * 16 + q4 + (wid & 1) * 2;   // STS.64 slot

    for (int t = 0; t < TT; ++t) {
        cp_wait<0>();
        __syncthreads();

        const uint32_t* Ar = As + (t & 1) * AS_W;
        uint32_t* Aw = As + ((t + 1) & 1) * AS_W;

        const float* xb = xs + (t & 1) * XS_F + brow * XS_ROW;
        float acc[3][4];
#pragma unroll
        for (int nc = 0; nc < 3; ++nc) {
            const float2 xv = *(const float2*)&xb[nc * 128 + ucol];
            acc[nc][0] = xv.x; acc[nc][1] = xv.y;
            acc[nc][2] = 0.f;  acc[nc][3] = 0.f;
        }

        if (t + 1 < TT) {
            if (((t + 1) & 127) == 0) {
                wait_chunk((t + 1) >> 7, b0g, tid);
                __syncthreads();
            }
            PREFETCH(t + 1);
        }

#pragma unroll
        for (int kc = 0; kc < 8; ++kc) {
            const uint4 av = *(const uint4*)&Ar[brow * AS_ROW + kc * 16 + q4];
            uint32_t af[4] = {av.x, av.y, av.z, av.w};
#pragma unroll
            for (int nc = 0; nc < 3; ++nc)
                mma_bf16(acc[nc], af, wfr[kc][nc]);
        }

        float gv[3][2];
#pragma unroll
        for (int nc = 0; nc < 3; ++nc) {
            const float p = pp[nc], q = qq[nc];
            const float g0 = acc[nc][0] + acc[nc][2];   // bias already in x
            const float g1 = acc[nc][1] + acc[nc][3];
            gv[nc][0] = fmaf(tanh_apx(g0 * p), p, q);
            gv[nc][1] = fmaf(tanh_apx(g1 * p), p, q);
        }

        const float2 fv =
            *(const float2*)&fs[(t & 1) * FS_F + brow * FS_ROW + ucol];
        cst[0] = fmaf(fv.x, cst[0], gv[0][0] * gv[1][0]);
        cst[1] = fmaf(fv.y, cst[1], gv[0][1] * gv[1][1]);
        const float h0 = gv[2][0] * tanh_apx(cst[0]);
        const float h1 = gv[2][1] * tanh_apx(cst[1]);

        // critical path first: pack + STS to As
        uint2 hv;
        pack2(h0, h1, hv.x, hv.y);
        *(uint2*)&Aw[brow * AS_ROW + wsl] = hv;

        // off-path: output store
        *(float2*)&out[((size_t)(b0g + brow) * TT + t) * UU + ucol] =
            make_float2(h0, h1);
    }

    // restore flags==0 invariant for the next graph replay (each (chunk,batch)
    // flag has reached 4 => no more writers; safe to zero here).
    __syncthreads();
    if (tid < 64) {
        const int c = tid >> 3;
        g_flags[c * 256 + b0g + (tid & 7)] = 0;
    }
}

// ---------------------------------------------------------------------------
// Megakernel: one wave of 148 CTAs (141KB smem => 1 CTA/SM).
// bids [0,32): scan. bids [32,148): workers over 8192 jobs, chunk-major:
// job = (chunk, batch, kind); kind 0..2 = gemm N-tiles, kind 3 = fgate tile.
// ---------------------------------------------------------------------------
__global__ __launch_bounds__(512, 1)
void mega_kernel(const float* __restrict__ inputs,
                 const float* __restrict__ signatures,
                 const float* __restrict__ rkern,
                 const float* __restrict__ fkern,
                 const float* __restrict__ bias,
                 float* __restrict__ out) {
    extern __shared__ __align__(16) char dsm[];
    const int bid = blockIdx.x;
    const int tid = threadIdx.x;

    if (bid < NSCAN) {
        scan_body(dsm, rkern, out, bid, tid);
    } else {
        float wk[20];
        const int uf = tid & 127;
#pragma unroll
        for (int k = 0; k < 20; ++k) wk[k] = __ldg(&fkern[k * UU + uf]);
        const float bf = __ldg(&bias[UU + uf]);

        for (int tau = bid - NSCAN; tau < NJOB; tau += NWORK) {
            const int chunk = tau >> 10;
            const int j     = tau & 1023;
            const int b     = j >> 2;
            const int kind  = j & 3;
            if (kind < 3) {
                gemm_tile(dsm, inputs, bias, kind * 128,
                          b * 1024 + chunk * 128, tid);
            } else {
                f_tile(dsm, signatures, wk, bf, b, chunk, tid);
            }
            __syncthreads();
            if (tid == 0) {
                __threadfence();
                atomicAdd(&g_flags[chunk * 256 + b], 1);
            }
        }
    }
}

// ---------------------------------------------------------------------------
extern "C" void kernel_launch(void* const* d_in, const int* in_sizes, int n_in,
                              void* d_out, int out_size) {
    const float* inputs     = (const float*)d_in[0];
    const float* signatures = (const float*)d_in[1];
    const float* ikern      = (const float*)d_in[2];
    const float* rkern      = (const float*)d_in[3];
    const float* fkern      = (const float*)d_in[4];
    const float* bias       = (const float*)d_in[5];
    float* out = (float*)d_out;

    (void)in_sizes; (void)n_in; (void)out_size;

    static bool init = false;
    if (!init) {
        cudaFuncSetAttribute(mega_kernel,
                             cudaFuncAttributeMaxDynamicSharedMemorySize,
                             MEGA_SMEM);
        init = true;
    }

    convert_b<<<GG, DD>>>(ikern);
    mega_kernel<<<NBLK, 512, MEGA_SMEM>>>(inputs, signatures, rkern, fkern,
                                          bias, out);
}